// round 1
// baseline (speedup 1.0000x reference)
#include <cuda_runtime.h>
#include <cstdint>

// Problem constants
#define NB    8
#define ND    256          // embedding dim (channels)
#define NTHW  16384        // 16*32*32
#define NTOK  131072       // 8 * 16384 tokens
#define NK    1024         // codebook size
#define NTOT  (NTOK * ND)  // 33554432 output tensor elements

// Tiling for the distance GEMM / argmin kernel
#define TN 128   // tokens per block
#define TK 64    // codewords per k-tile
#define CK 32    // channels per smem chunk

// Device scratch (allocation-free rule: __device__ globals)
__device__ int    g_idx[NTOK];
__device__ float  g_A[NTOK];
__device__ float  g_B[NK];
__device__ double g_loss;

// ---------------------------------------------------------------------------
// Kernel 0: zero loss accumulator + compute B_k = sum_c emb[k][c]^2
// Replicates reference rounding: fl(square) then sequential fl(add).
// (B ~ 8.5e-5; its reduction-order sensitivity is ~1e-11 — negligible vs the
//  3e-5 distance ulp, so sequential order is safe here.)
// ---------------------------------------------------------------------------
__global__ void k_init(const float* __restrict__ emb) {
    int k = blockIdx.x * blockDim.x + threadIdx.x;
    if (k == 0) g_loss = 0.0;
    if (k < NK) {
        const float* r = emb + (size_t)k * ND;
        float a = 0.f;
        #pragma unroll 8
        for (int c = 0; c < ND; c++) {
            float v = r[c];
            a = __fadd_rn(a, __fmul_rn(v, v));
        }
        g_B[k] = a;
    }
}

// ---------------------------------------------------------------------------
// Kernel 1: A_n = sum_c x[n][c]^2, replicating XLA's GPU row-reduce pattern:
// lane l accumulates c = l, l+32, ..., l+224 sequentially (rounded square,
// rounded add), then a shfl_down tree (16,8,4,2,1).
// Block: 256 threads = 8 warps; 32 tokens per block; smem transpose so the
// global loads are coalesced while the reduction runs channel-across-lanes.
// ---------------------------------------------------------------------------
__global__ __launch_bounds__(256) void k_A(const float* __restrict__ x) {
    __shared__ float xs[ND * 33];  // [c][t] padded, 32 tokens
    int tid = threadIdx.x;
    int n0  = blockIdx.x * 32;
    int b   = n0 / NTHW;
    int p0  = n0 % NTHW;
    const float* xb = x + (size_t)b * ND * NTHW + p0;

    for (int l = tid; l < ND * 32; l += 256) {
        int c = l >> 5, t = l & 31;
        xs[c * 33 + t] = xb[(size_t)c * NTHW + t];   // coalesced 128B per c
    }
    __syncthreads();

    int w = tid >> 5, lane = tid & 31;
    #pragma unroll
    for (int rr = 0; rr < 4; rr++) {
        int t = w * 4 + rr;
        float s = 0.f;
        #pragma unroll
        for (int u = 0; u < 8; u++) {
            float v = xs[(lane + 32 * u) * 33 + t];  // conflict-free: (lane+t)%32
            s = __fadd_rn(s, __fmul_rn(v, v));
        }
        #pragma unroll
        for (int off = 16; off > 0; off >>= 1)
            s = __fadd_rn(s, __shfl_down_sync(0xffffffffu, s, off));
        if (lane == 0) g_A[n0 + t] = s;
    }
}

// ---------------------------------------------------------------------------
// Kernel 2: distance GEMM + argmin.
// Block: 256 threads handles TN=128 tokens x all 1024 codes.
// Full x tile (256c x 128t = 128KB) resident in smem; emb streamed in
// TKxCK chunks (L2-resident, 1MB total).
// Thread tile: 8 tokens x 4 codes; dot accumulated fp32 FFMA, c ascending
// (sequential chain, matching cublas-style fused accumulation semantics).
// d = fl(fl(A + B_k) - 2*M) exactly as the reference; argmin keeps the
// lowest index on exact float ties (lexicographic (d, k) reduce).
// ---------------------------------------------------------------------------
__global__ __launch_bounds__(256, 1) void k_argmin(const float* __restrict__ x,
                                                   const float* __restrict__ emb) {
    extern __shared__ float sm[];
    float* xs = sm;                         // ND * TN            = 32768
    float* es = xs + ND * TN;               // TK * (CK+1)        = 2112
    float* cd = es + TK * (CK + 1);         // TN * 16            = 2048
    int*   cI = (int*)(cd + TN * 16);       // TN * 16            = 2048

    int tid = threadIdx.x;
    int n0  = blockIdx.x * TN;
    int b   = n0 / NTHW;
    int p0  = n0 % NTHW;
    const float* xb = x + (size_t)b * ND * NTHW + p0;

    // Load x tile: xs[c*TN + p], coalesced float4 (512B per channel row)
    for (int l = tid; l < ND * TN / 4; l += 256) {
        int c = l / (TN / 4);
        int p4 = l % (TN / 4);
        float4 v = *reinterpret_cast<const float4*>(xb + (size_t)c * NTHW + p4 * 4);
        *reinterpret_cast<float4*>(xs + c * TN + p4 * 4) = v;
    }
    __syncthreads();

    int tx = tid & 15;   // code group: k = kt*64 + tx*4 + j
    int ty = tid >> 4;   // token group: t = ty*8 + i

    float Areg[8];
    #pragma unroll
    for (int i = 0; i < 8; i++) Areg[i] = g_A[n0 + ty * 8 + i];

    float bestd[8];
    int   besti[8];
    #pragma unroll
    for (int i = 0; i < 8; i++) { bestd[i] = __int_as_float(0x7f800000); besti[i] = 0; }

    for (int kt = 0; kt < NK / TK; kt++) {
        float acc[8][4];
        #pragma unroll
        for (int i = 0; i < 8; i++)
            #pragma unroll
            for (int j = 0; j < 4; j++) acc[i][j] = 0.f;

        for (int cc = 0; cc < ND; cc += CK) {
            __syncthreads();
            // load emb chunk: es[r*(CK+1)+c] = emb[kt*64+r][cc+c], coalesced
            for (int l = tid; l < TK * CK; l += 256) {
                int r = l / CK, c = l % CK;
                es[r * (CK + 1) + c] = emb[(size_t)(kt * TK + r) * ND + cc + c];
            }
            __syncthreads();

            #pragma unroll 16
            for (int u = 0; u < CK; u++) {
                int c = cc + u;
                float4 xa = *reinterpret_cast<const float4*>(xs + c * TN + ty * 8);
                float4 xv2 = *reinterpret_cast<const float4*>(xs + c * TN + ty * 8 + 4);
                float ev0 = es[(tx * 4 + 0) * (CK + 1) + u];
                float ev1 = es[(tx * 4 + 1) * (CK + 1) + u];
                float ev2 = es[(tx * 4 + 2) * (CK + 1) + u];
                float ev3 = es[(tx * 4 + 3) * (CK + 1) + u];
                float xv[8] = {xa.x, xa.y, xa.z, xa.w, xv2.x, xv2.y, xv2.z, xv2.w};
                #pragma unroll
                for (int i = 0; i < 8; i++) {
                    acc[i][0] = fmaf(xv[i], ev0, acc[i][0]);
                    acc[i][1] = fmaf(xv[i], ev1, acc[i][1]);
                    acc[i][2] = fmaf(xv[i], ev2, acc[i][2]);
                    acc[i][3] = fmaf(xv[i], ev3, acc[i][3]);
                }
            }
        }

        // distances + running argmin (k ascending within thread -> strict <)
        #pragma unroll
        for (int j = 0; j < 4; j++) {
            int k = kt * TK + tx * 4 + j;
            float Bk = g_B[k];
            #pragma unroll
            for (int i = 0; i < 8; i++) {
                float ab = __fadd_rn(Areg[i], Bk);                       // fl(A + B)
                float d  = __fadd_rn(ab, __fmul_rn(-2.0f, acc[i][j]));   // fl(.. - 2M)
                if (d < bestd[i]) { bestd[i] = d; besti[i] = k; }
            }
        }
    }

    // cross-thread lexicographic (d, k) reduce per token
    #pragma unroll
    for (int i = 0; i < 8; i++) {
        int t = ty * 8 + i;
        cd[t * 16 + tx] = bestd[i];
        cI[t * 16 + tx] = besti[i];
    }
    __syncthreads();
    if (tid < TN) {
        float bd = cd[tid * 16];
        int   bi = cI[tid * 16];
        #pragma unroll
        for (int j = 1; j < 16; j++) {
            float d = cd[tid * 16 + j];
            int   k = cI[tid * 16 + j];
            if (d < bd || (d == bd && k < bi)) { bd = d; bi = k; }
        }
        g_idx[n0 + tid] = bi;
    }
}

// ---------------------------------------------------------------------------
// Kernel 3: gather codewords, straight-through output, loss accumulation.
// out = fl(x + fl(q - x))  (replicates the ST estimator's rounding exactly);
// loss accumulates fl((q-x)^2) in double.
// Block: 256 threads, 32 tokens x 256 channels; emb rows staged via smem
// (conflict-free warp-per-row loads, padded [32][257] for the [t][c] reads).
// ---------------------------------------------------------------------------
__global__ __launch_bounds__(256) void k_gather(const float* __restrict__ x,
                                                const float* __restrict__ emb,
                                                float* __restrict__ out) {
    __shared__ float qs[32][257];
    __shared__ int   idxs[32];
    __shared__ double red[8];

    int tid = threadIdx.x;
    int n0  = blockIdx.x * 32;
    if (tid < 32) idxs[tid] = g_idx[n0 + tid];
    __syncthreads();

    int w = tid >> 5, lane = tid & 31;
    #pragma unroll
    for (int rr = 0; rr < 4; rr++) {
        int r = w * 4 + rr;
        const float* er = emb + (size_t)idxs[r] * ND;
        #pragma unroll
        for (int u = 0; u < 8; u++)
            qs[r][lane + 32 * u] = er[lane + 32 * u];   // coalesced, bank (r+lane)%32
    }
    __syncthreads();

    int b  = n0 / NTHW;
    int p0 = n0 % NTHW;
    const float* xb = x   + (size_t)b * ND * NTHW + p0;
    float*       ob = out + (size_t)b * ND * NTHW + p0;

    double lacc = 0.0;
    for (int o = tid; o < 32 * ND; o += 256) {
        int c = o >> 5, t = o & 31;
        float xv = xb[(size_t)c * NTHW + t];        // coalesced 128B
        float q  = qs[t][c];                        // bank (t+c)%32: conflict-free
        float df = __fsub_rn(q, xv);
        ob[(size_t)c * NTHW + t] = __fadd_rn(xv, df);
        lacc += (double)__fmul_rn(df, df);
    }

    #pragma unroll
    for (int off = 16; off > 0; off >>= 1)
        lacc += __shfl_down_sync(0xffffffffu, lacc, off);
    if (lane == 0) red[w] = lacc;
    __syncthreads();
    if (tid == 0) {
        double s = 0.0;
        #pragma unroll
        for (int i = 0; i < 8; i++) s += red[i];
        atomicAdd(&g_loss, s);
    }
}

// ---------------------------------------------------------------------------
// Kernel 4: finalize loss = fl(m + fl(0.25*m)), m = mean((q-x)^2)
// ---------------------------------------------------------------------------
__global__ void k_final(float* __restrict__ out, int out_size) {
    if (out_size > NTOT) {
        float m = (float)(g_loss / (double)NTOT);
        out[NTOT] = __fadd_rn(m, __fmul_rn(0.25f, m));
    }
}

// ---------------------------------------------------------------------------
extern "C" void kernel_launch(void* const* d_in, const int* in_sizes, int n_in,
                              void* d_out, int out_size) {
    const float* x   = (const float*)d_in[0];
    const float* emb = (const float*)d_in[1];
    if (n_in >= 2 && in_sizes[0] == NK * ND && in_sizes[1] == NTOT) {
        // metadata order was emb-first; swap
        x   = (const float*)d_in[1];
        emb = (const float*)d_in[0];
    }
    float* out = (float*)d_out;

    // Dynamic smem for the argmin GEMM tile (xs 128KB + es + reduce arrays)
    const int SMEM_ARGMIN = (ND * TN + TK * (CK + 1) + TN * 16 + TN * 16) * 4; // 155904 B
    cudaFuncSetAttribute(k_argmin, cudaFuncAttributeMaxDynamicSharedMemorySize, SMEM_ARGMIN);

    k_init  <<<(NK + 255) / 256, 256>>>(emb);
    k_A     <<<NTOK / 32, 256>>>(x);
    k_argmin<<<NTOK / TN, 256, SMEM_ARGMIN>>>(x, emb);
    k_gather<<<NTOK / 32, 256>>>(x, emb, out);
    k_final <<<1, 1>>>(out, out_size);
}

// round 2
// speedup vs baseline: 1.0016x; 1.0016x over previous
#include <cuda_runtime.h>
#include <cstdint>

// Problem constants
#define NB    8
#define ND    256          // embedding dim (channels)
#define NTHW  16384        // 16*32*32
#define NTOK  131072       // 8 * 16384 tokens
#define NK    1024         // codebook size
#define NTOT  (NTOK * ND)  // 33554432 output tensor elements

// Tiling for the distance GEMM / argmin kernel
#define TN 128   // tokens per block
#define TK 64    // codewords per k-tile
#define CK 32    // channels per smem chunk

// Device scratch (allocation-free rule: __device__ globals)
__device__ int    g_idx[NTOK];
__device__ float  g_A[NTOK];
__device__ float  g_B[NK];
__device__ double g_loss;

// ---------------------------------------------------------------------------
// Kernel 0: zero loss accumulator + compute B_k = sum_c emb[k][c]^2
// Replicates reference rounding: fl(square) then sequential fl(add).
// (B ~ 8.5e-5; its reduction-order sensitivity is ~1e-11 — negligible vs the
//  3e-5 distance ulp, so sequential order is safe here.)
// ---------------------------------------------------------------------------
__global__ void k_init(const float* __restrict__ emb) {
    int k = blockIdx.x * blockDim.x + threadIdx.x;
    if (k == 0) g_loss = 0.0;
    if (k < NK) {
        const float* r = emb + (size_t)k * ND;
        float a = 0.f;
        #pragma unroll 8
        for (int c = 0; c < ND; c++) {
            float v = r[c];
            a = __fadd_rn(a, __fmul_rn(v, v));
        }
        g_B[k] = a;
    }
}

// ---------------------------------------------------------------------------
// Kernel 1: A_n = sum_c x[n][c]^2, replicating XLA's GPU row-reduce pattern:
// lane l accumulates c = l, l+32, ..., l+224 sequentially (rounded square,
// rounded add), then a shfl_down tree (16,8,4,2,1).
// Block: 256 threads = 8 warps; 32 tokens per block; smem transpose so the
// global loads are coalesced while the reduction runs channel-across-lanes.
// ---------------------------------------------------------------------------
__global__ __launch_bounds__(256) void k_A(const float* __restrict__ x) {
    __shared__ float xs[ND * 33];  // [c][t] padded, 32 tokens
    int tid = threadIdx.x;
    int n0  = blockIdx.x * 32;
    int b   = n0 / NTHW;
    int p0  = n0 % NTHW;
    const float* xb = x + (size_t)b * ND * NTHW + p0;

    for (int l = tid; l < ND * 32; l += 256) {
        int c = l >> 5, t = l & 31;
        xs[c * 33 + t] = xb[(size_t)c * NTHW + t];   // coalesced 128B per c
    }
    __syncthreads();

    int w = tid >> 5, lane = tid & 31;
    #pragma unroll
    for (int rr = 0; rr < 4; rr++) {
        int t = w * 4 + rr;
        float s = 0.f;
        #pragma unroll
        for (int u = 0; u < 8; u++) {
            float v = xs[(lane + 32 * u) * 33 + t];  // conflict-free: (lane+t)%32
            s = __fadd_rn(s, __fmul_rn(v, v));
        }
        #pragma unroll
        for (int off = 16; off > 0; off >>= 1)
            s = __fadd_rn(s, __shfl_down_sync(0xffffffffu, s, off));
        if (lane == 0) g_A[n0 + t] = s;
    }
}

// ---------------------------------------------------------------------------
// Kernel 2: distance GEMM + argmin.
// Block: 256 threads handles TN=128 tokens x all 1024 codes.
// Full x tile (256c x 128t = 128KB) resident in smem; emb streamed in
// TKxCK chunks (L2-resident, 1MB total).
// Thread tile: 8 tokens x 4 codes; dot accumulated fp32 FFMA, c ascending
// (sequential chain, matching cublas-style fused accumulation semantics).
// d = fl(fl(A + B_k) - 2*M) exactly as the reference; argmin keeps the
// lowest index on exact float ties (lexicographic (d, k) reduce).
// ---------------------------------------------------------------------------
__global__ __launch_bounds__(256, 1) void k_argmin(const float* __restrict__ x,
                                                   const float* __restrict__ emb) {
    extern __shared__ float sm[];
    float* xs = sm;                         // ND * TN            = 32768
    float* es = xs + ND * TN;               // TK * (CK+1)        = 2112
    float* cd = es + TK * (CK + 1);         // TN * 16            = 2048
    int*   cI = (int*)(cd + TN * 16);       // TN * 16            = 2048

    int tid = threadIdx.x;
    int n0  = blockIdx.x * TN;
    int b   = n0 / NTHW;
    int p0  = n0 % NTHW;
    const float* xb = x + (size_t)b * ND * NTHW + p0;

    // Load x tile: xs[c*TN + p], coalesced float4 (512B per channel row)
    for (int l = tid; l < ND * TN / 4; l += 256) {
        int c = l / (TN / 4);
        int p4 = l % (TN / 4);
        float4 v = *reinterpret_cast<const float4*>(xb + (size_t)c * NTHW + p4 * 4);
        *reinterpret_cast<float4*>(xs + c * TN + p4 * 4) = v;
    }
    __syncthreads();

    int tx = tid & 15;   // code group: k = kt*64 + tx*4 + j
    int ty = tid >> 4;   // token group: t = ty*8 + i

    float Areg[8];
    #pragma unroll
    for (int i = 0; i < 8; i++) Areg[i] = g_A[n0 + ty * 8 + i];

    float bestd[8];
    int   besti[8];
    #pragma unroll
    for (int i = 0; i < 8; i++) { bestd[i] = __int_as_float(0x7f800000); besti[i] = 0; }

    for (int kt = 0; kt < NK / TK; kt++) {
        float acc[8][4];
        #pragma unroll
        for (int i = 0; i < 8; i++)
            #pragma unroll
            for (int j = 0; j < 4; j++) acc[i][j] = 0.f;

        for (int cc = 0; cc < ND; cc += CK) {
            __syncthreads();
            // load emb chunk: es[r*(CK+1)+c] = emb[kt*64+r][cc+c], coalesced
            for (int l = tid; l < TK * CK; l += 256) {
                int r = l / CK, c = l % CK;
                es[r * (CK + 1) + c] = emb[(size_t)(kt * TK + r) * ND + cc + c];
            }
            __syncthreads();

            #pragma unroll 16
            for (int u = 0; u < CK; u++) {
                int c = cc + u;
                float4 xa = *reinterpret_cast<const float4*>(xs + c * TN + ty * 8);
                float4 xv2 = *reinterpret_cast<const float4*>(xs + c * TN + ty * 8 + 4);
                float ev0 = es[(tx * 4 + 0) * (CK + 1) + u];
                float ev1 = es[(tx * 4 + 1) * (CK + 1) + u];
                float ev2 = es[(tx * 4 + 2) * (CK + 1) + u];
                float ev3 = es[(tx * 4 + 3) * (CK + 1) + u];
                float xv[8] = {xa.x, xa.y, xa.z, xa.w, xv2.x, xv2.y, xv2.z, xv2.w};
                #pragma unroll
                for (int i = 0; i < 8; i++) {
                    acc[i][0] = fmaf(xv[i], ev0, acc[i][0]);
                    acc[i][1] = fmaf(xv[i], ev1, acc[i][1]);
                    acc[i][2] = fmaf(xv[i], ev2, acc[i][2]);
                    acc[i][3] = fmaf(xv[i], ev3, acc[i][3]);
                }
            }
        }

        // distances + running argmin (k ascending within thread -> strict <)
        #pragma unroll
        for (int j = 0; j < 4; j++) {
            int k = kt * TK + tx * 4 + j;
            float Bk = g_B[k];
            #pragma unroll
            for (int i = 0; i < 8; i++) {
                float ab = __fadd_rn(Areg[i], Bk);                       // fl(A + B)
                float d  = __fadd_rn(ab, __fmul_rn(-2.0f, acc[i][j]));   // fl(.. - 2M)
                if (d < bestd[i]) { bestd[i] = d; besti[i] = k; }
            }
        }
    }

    // cross-thread lexicographic (d, k) reduce per token
    #pragma unroll
    for (int i = 0; i < 8; i++) {
        int t = ty * 8 + i;
        cd[t * 16 + tx] = bestd[i];
        cI[t * 16 + tx] = besti[i];
    }
    __syncthreads();
    if (tid < TN) {
        float bd = cd[tid * 16];
        int   bi = cI[tid * 16];
        #pragma unroll
        for (int j = 1; j < 16; j++) {
            float d = cd[tid * 16 + j];
            int   k = cI[tid * 16 + j];
            if (d < bd || (d == bd && k < bi)) { bd = d; bi = k; }
        }
        g_idx[n0 + tid] = bi;
    }
}

// ---------------------------------------------------------------------------
// Kernel 3: gather codewords, straight-through output, loss accumulation.
// out = fl(x + fl(q - x))  (replicates the ST estimator's rounding exactly);
// loss accumulates fl((q-x)^2) in double.
// Block: 256 threads, 32 tokens x 256 channels; emb rows staged via smem
// (conflict-free warp-per-row loads, padded [32][257] for the [t][c] reads).
// ---------------------------------------------------------------------------
__global__ __launch_bounds__(256) void k_gather(const float* __restrict__ x,
                                                const float* __restrict__ emb,
                                                float* __restrict__ out) {
    __shared__ float qs[32][257];
    __shared__ int   idxs[32];
    __shared__ double red[8];

    int tid = threadIdx.x;
    int n0  = blockIdx.x * 32;
    if (tid < 32) idxs[tid] = g_idx[n0 + tid];
    __syncthreads();

    int w = tid >> 5, lane = tid & 31;
    #pragma unroll
    for (int rr = 0; rr < 4; rr++) {
        int r = w * 4 + rr;
        const float* er = emb + (size_t)idxs[r] * ND;
        #pragma unroll
        for (int u = 0; u < 8; u++)
            qs[r][lane + 32 * u] = er[lane + 32 * u];   // coalesced, bank (r+lane)%32
    }
    __syncthreads();

    int b  = n0 / NTHW;
    int p0 = n0 % NTHW;
    const float* xb = x   + (size_t)b * ND * NTHW + p0;
    float*       ob = out + (size_t)b * ND * NTHW + p0;

    double lacc = 0.0;
    for (int o = tid; o < 32 * ND; o += 256) {
        int c = o >> 5, t = o & 31;
        float xv = xb[(size_t)c * NTHW + t];        // coalesced 128B
        float q  = qs[t][c];                        // bank (t+c)%32: conflict-free
        float df = __fsub_rn(q, xv);
        ob[(size_t)c * NTHW + t] = __fadd_rn(xv, df);
        lacc += (double)__fmul_rn(df, df);
    }

    #pragma unroll
    for (int off = 16; off > 0; off >>= 1)
        lacc += __shfl_down_sync(0xffffffffu, lacc, off);
    if (lane == 0) red[w] = lacc;
    __syncthreads();
    if (tid == 0) {
        double s = 0.0;
        #pragma unroll
        for (int i = 0; i < 8; i++) s += red[i];
        atomicAdd(&g_loss, s);
    }
}

// ---------------------------------------------------------------------------
// Kernel 4: finalize loss = fl(m + fl(0.25*m)), m = mean((q-x)^2)
// ---------------------------------------------------------------------------
__global__ void k_final(float* __restrict__ out, int out_size) {
    if (out_size > NTOT) {
        float m = (float)(g_loss / (double)NTOT);
        out[NTOT] = __fadd_rn(m, __fmul_rn(0.25f, m));
    }
}

// ---------------------------------------------------------------------------
extern "C" void kernel_launch(void* const* d_in, const int* in_sizes, int n_in,
                              void* d_out, int out_size) {
    const float* x   = (const float*)d_in[0];
    const float* emb = (const float*)d_in[1];
    if (n_in >= 2 && in_sizes[0] == NK * ND && in_sizes[1] == NTOT) {
        // metadata order was emb-first; swap
        x   = (const float*)d_in[1];
        emb = (const float*)d_in[0];
    }
    float* out = (float*)d_out;

    // Dynamic smem for the argmin GEMM tile (xs 128KB + es + reduce arrays)
    const int SMEM_ARGMIN = (ND * TN + TK * (CK + 1) + TN * 16 + TN * 16) * 4; // 155904 B
    cudaFuncSetAttribute(k_argmin, cudaFuncAttributeMaxDynamicSharedMemorySize, SMEM_ARGMIN);

    k_init  <<<(NK + 255) / 256, 256>>>(emb);
    k_A     <<<NTOK / 32, 256>>>(x);
    k_argmin<<<NTOK / TN, 256, SMEM_ARGMIN>>>(x, emb);
    k_gather<<<NTOK / 32, 256>>>(x, emb, out);
    k_final <<<1, 1>>>(out, out_size);
}